// round 1
// baseline (speedup 1.0000x reference)
#include <cuda_runtime.h>

// Problem constants (match reference)
#define NN 100000
#define EE 3200000
#define GG 2048
#define HH 64

// Scratch (device globals — no allocation allowed)
__device__ float d_h[NN * HH];     // node features
__device__ float d_u[NN * HH];     // (h @ W) * dinv
__device__ float d_agg[NN * HH];   // scatter accumulator
__device__ float d_dinv[NN];       // degree -> rsqrt(deg)
__device__ float d_sums[GG * HH];  // pooled sums
__device__ float d_cnt[GG];        // pooled counts

__device__ __forceinline__ void red4(float* addr, float4 v) {
    asm volatile("red.global.add.v4.f32 [%0], {%1,%2,%3,%4};"
                 :: "l"(addr), "f"(v.x), "f"(v.y), "f"(v.z), "f"(v.w)
                 : "memory");
}

// ---------------------------------------------------------------- init
__global__ void k_init(int n) {
    int i = blockIdx.x * blockDim.x + threadIdx.x;
    float4 z = make_float4(0.f, 0.f, 0.f, 0.f);
    if (i < n * (HH / 4)) ((float4*)d_agg)[i] = z;
    if (i < n) d_dinv[i] = 1.0f;  // self-loop contributes 1 to degree
    if (i < GG * (HH / 4)) ((float4*)d_sums)[i] = z;
    if (i < GG) d_cnt[i] = 0.f;
}

// degree count over targets (col)
__global__ void k_deg(const int* __restrict__ col, int e_cnt) {
    int e = blockIdx.x * blockDim.x + threadIdx.x;
    if (e < e_cnt) atomicAdd(&d_dinv[col[e]], 1.0f);
}

__global__ void k_rsq(int n) {
    int i = blockIdx.x * blockDim.x + threadIdx.x;
    if (i < n) d_dinv[i] = rsqrtf(d_dinv[i]);
}

// h = emb[x]
__global__ void k_embed(const int* __restrict__ x, const float* __restrict__ emb, int n) {
    int i = blockIdx.x * blockDim.x + threadIdx.x;
    if (i >= n * 16) return;
    int nd = i >> 4, j = i & 15;
    int v = __ldg(&x[nd]);
    ((float4*)d_h)[i] = __ldg(&((const float4*)emb)[v * 16 + j]);
}

// ---------------------------------------------------------------- GEMM
// u = (h @ W) * dinv[:,None]
// block: 256 threads, 64 rows x 64 cols; thread = (row local r = tid>>2, col quad q = tid&3)
__global__ void __launch_bounds__(256) k_gemm(const float* __restrict__ W, int n) {
    __shared__ float4 sW[64 * 16];     // W[k][j], 16KB
    __shared__ float sh[64 * 68];      // h rows, padded stride 68 (bank-safe, f4-aligned)

    int tid = threadIdx.x;
    int row0 = blockIdx.x * 64;

    const float4* W4 = (const float4*)W;
#pragma unroll
    for (int i = 0; i < 4; i++) sW[tid + 256 * i] = W4[tid + 256 * i];

    const float4* h4 = (const float4*)d_h;
#pragma unroll
    for (int i = 0; i < 4; i++) {
        int l = tid + 256 * i;
        int r = l >> 4, c4 = l & 15;
        float4 v = make_float4(0.f, 0.f, 0.f, 0.f);
        if (row0 + r < n) v = h4[(row0 + r) * 16 + c4];
        ((float4*)sh)[r * 17 + c4] = v;
    }
    __syncthreads();

    int r = tid >> 2, q = tid & 3;
    float4 a0 = make_float4(0.f, 0.f, 0.f, 0.f), a1 = a0, a2 = a0, a3 = a0;

#pragma unroll 16
    for (int k = 0; k < 64; k++) {
        float hv = sh[r * 68 + k];
        float4 w0 = sW[k * 16 + q * 4 + 0];
        float4 w1 = sW[k * 16 + q * 4 + 1];
        float4 w2 = sW[k * 16 + q * 4 + 2];
        float4 w3 = sW[k * 16 + q * 4 + 3];
        a0.x = fmaf(hv, w0.x, a0.x); a0.y = fmaf(hv, w0.y, a0.y);
        a0.z = fmaf(hv, w0.z, a0.z); a0.w = fmaf(hv, w0.w, a0.w);
        a1.x = fmaf(hv, w1.x, a1.x); a1.y = fmaf(hv, w1.y, a1.y);
        a1.z = fmaf(hv, w1.z, a1.z); a1.w = fmaf(hv, w1.w, a1.w);
        a2.x = fmaf(hv, w2.x, a2.x); a2.y = fmaf(hv, w2.y, a2.y);
        a2.z = fmaf(hv, w2.z, a2.z); a2.w = fmaf(hv, w2.w, a2.w);
        a3.x = fmaf(hv, w3.x, a3.x); a3.y = fmaf(hv, w3.y, a3.y);
        a3.z = fmaf(hv, w3.z, a3.z); a3.w = fmaf(hv, w3.w, a3.w);
    }

    int row = row0 + r;
    if (row < n) {
        float dv = __ldg(&d_dinv[row]);
        float4* u4 = (float4*)d_u;
        a0.x *= dv; a0.y *= dv; a0.z *= dv; a0.w *= dv;
        a1.x *= dv; a1.y *= dv; a1.z *= dv; a1.w *= dv;
        a2.x *= dv; a2.y *= dv; a2.z *= dv; a2.w *= dv;
        a3.x *= dv; a3.y *= dv; a3.z *= dv; a3.w *= dv;
        u4[row * 16 + q * 4 + 0] = a0;
        u4[row * 16 + q * 4 + 1] = a1;
        u4[row * 16 + q * 4 + 2] = a2;
        u4[row * 16 + q * 4 + 3] = a3;
    }
}

// ---------------------------------------------------------------- scatter
// 16 lanes per edge: gather u[row] (float4/lane), vector-reduce into agg[col]
__global__ void __launch_bounds__(256) k_scatter(const int* __restrict__ rowi,
                                                 const int* __restrict__ coli,
                                                 int e_cnt) {
    int idx = blockIdx.x * blockDim.x + threadIdx.x;
    int e = idx >> 4;
    if (e >= e_cnt) return;
    int p = idx & 15;
    int r = __ldg(&rowi[e]);
    int c = __ldg(&coli[e]);
    float4 v = __ldg(&((const float4*)d_u)[r * 16 + p]);
    red4(&d_agg[c * 64 + p * 4], v);
}

// ---------------------------------------------------------------- epilogue
// h_new = relu(dinv*(agg + u) + b);  h = (layer==0) ? h_new : h + h_new;  agg = 0
__global__ void k_epi(const float* __restrict__ b, int layer, int n) {
    int i = blockIdx.x * blockDim.x + threadIdx.x;
    if (i >= n * 16) return;
    int nd = i >> 4, j = i & 15;
    float4* u4 = (float4*)d_u;
    float4* agg4 = (float4*)d_agg;
    float4* h4 = (float4*)d_h;

    float4 uu = u4[i];
    float4 ag = agg4[i];
    float dv = __ldg(&d_dinv[nd]);
    float4 bb = __ldg(&((const float4*)b)[j]);

    float4 v;
    v.x = fmaxf(fmaf(dv, ag.x + uu.x, bb.x), 0.f);
    v.y = fmaxf(fmaf(dv, ag.y + uu.y, bb.y), 0.f);
    v.z = fmaxf(fmaf(dv, ag.z + uu.z, bb.z), 0.f);
    v.w = fmaxf(fmaf(dv, ag.w + uu.w, bb.w), 0.f);

    if (layer != 0) {
        float4 hh = h4[i];
        v.x += hh.x; v.y += hh.y; v.z += hh.z; v.w += hh.w;
    }
    h4[i] = v;
    agg4[i] = make_float4(0.f, 0.f, 0.f, 0.f);  // ready for next layer
}

// ---------------------------------------------------------------- pool
__global__ void k_pool(const int* __restrict__ batch, int n) {
    int i = blockIdx.x * blockDim.x + threadIdx.x;
    if (i >= n * 16) return;
    int nd = i >> 4, p = i & 15;
    int g = __ldg(&batch[nd]);
    float4 v = ((const float4*)d_h)[i];
    red4(&d_sums[g * 64 + p * 4], v);
    if (p == 0) atomicAdd(&d_cnt[g], 1.0f);
}

// ---------------------------------------------------------------- MLP head
__global__ void k_mlp(const float* __restrict__ w1, const float* __restrict__ b1,
                      const float* __restrict__ w2, const float* __restrict__ b2,
                      const float* __restrict__ w3, const float* __restrict__ b3,
                      float* __restrict__ out) {
    int g = blockIdx.x * blockDim.x + threadIdx.x;
    if (g >= GG) return;

    float inv = 1.0f / fmaxf(d_cnt[g], 1.0f);
    float gin[64];
#pragma unroll
    for (int k = 0; k < 64; k++) gin[k] = d_sums[g * 64 + k] * inv;

    float a1[32];
#pragma unroll
    for (int j = 0; j < 32; j++) {
        float s = __ldg(&b1[j]);
#pragma unroll
        for (int k = 0; k < 64; k++) s = fmaf(gin[k], __ldg(&w1[k * 32 + j]), s);
        a1[j] = fmaxf(s, 0.f);
    }
    float a2[16];
#pragma unroll
    for (int j = 0; j < 16; j++) {
        float s = __ldg(&b2[j]);
#pragma unroll
        for (int k = 0; k < 32; k++) s = fmaf(a1[k], __ldg(&w2[k * 16 + j]), s);
        a2[j] = fmaxf(s, 0.f);
    }
    float s = __ldg(&b3[0]);
#pragma unroll
    for (int k = 0; k < 16; k++) s = fmaf(a2[k], __ldg(&w3[k]), s);
    out[g] = s;
}

// ---------------------------------------------------------------- launch
extern "C" void kernel_launch(void* const* d_in, const int* in_sizes, int n_in,
                              void* d_out, int out_size) {
    const int*   x      = (const int*)d_in[0];
    const int*   ei     = (const int*)d_in[1];
    const int*   batch  = (const int*)d_in[2];
    const float* emb    = (const float*)d_in[3];
    const float* conv_w = (const float*)d_in[4];
    const float* conv_b = (const float*)d_in[5];
    const float* w1     = (const float*)d_in[6];
    const float* b1     = (const float*)d_in[7];
    const float* w2     = (const float*)d_in[8];
    const float* b2     = (const float*)d_in[9];
    const float* w3     = (const float*)d_in[10];
    const float* b3     = (const float*)d_in[11];
    float* out = (float*)d_out;

    int n = in_sizes[0];       // 100000
    int e = in_sizes[1] / 2;   // 3200000
    const int* row = ei;       // source
    const int* col = ei + e;   // target

    int tb = 256;
    int g_nh = (n * 16 + tb - 1) / tb;     // N*H/4 threads
    int g_e  = (e + tb - 1) / tb;
    int g_e16 = (int)(((long long)e * 16 + tb - 1) / tb);
    int g_n  = (n + tb - 1) / tb;
    int g_rows = (n + 63) / 64;

    k_init<<<g_nh, tb>>>(n);
    k_deg<<<g_e, tb>>>(col, e);
    k_rsq<<<g_n, tb>>>(n);
    k_embed<<<g_nh, tb>>>(x, emb, n);

    for (int l = 0; l < 3; l++) {
        k_gemm<<<g_rows, tb>>>(conv_w + l * HH * HH, n);
        k_scatter<<<g_e16, tb>>>(row, col, e);
        k_epi<<<g_nh, tb>>>(conv_b + l * HH, l, n);
    }

    k_pool<<<g_nh, tb>>>(batch, n);
    k_mlp<<<(GG + tb - 1) / tb, tb>>>(w1, b1, w2, b2, w3, b3, out);
}

// round 2
// speedup vs baseline: 1.5682x; 1.5682x over previous
#include <cuda_runtime.h>

#define NN 100000
#define EE 3200000
#define GG 2048
#define HH 64
#define SCAN_BS 512

// Scratch (device globals — no allocation allowed)
__device__ float d_h[NN * HH];      // node features
__device__ float d_u[NN * HH];      // (h @ W) * dinv
__device__ float d_dinv[NN];        // rsqrt(deg+1)
__device__ int   d_degi[NN];        // in-degree (targets)
__device__ int   d_off[NN];         // CSR offsets (exclusive scan of degi)
__device__ int   d_cursor[NN];      // fill cursors
__device__ int   d_csr[EE];         // source node per incoming edge, grouped by target
__device__ int   d_bsum[1024];      // scan block sums
__device__ float d_sums[GG * HH];   // pooled sums
__device__ float d_cnt[GG];         // pooled counts

__device__ __forceinline__ void red4(float* addr, float4 v) {
    asm volatile("red.global.add.v4.f32 [%0], {%1,%2,%3,%4};"
                 :: "l"(addr), "f"(v.x), "f"(v.y), "f"(v.z), "f"(v.w)
                 : "memory");
}

// ---------------------------------------------------------------- init
__global__ void k_init(int n) {
    int i = blockIdx.x * blockDim.x + threadIdx.x;
    if (i < n) d_degi[i] = 0;
    if (i < GG * (HH / 4)) ((float4*)d_sums)[i] = make_float4(0.f, 0.f, 0.f, 0.f);
    if (i < GG) d_cnt[i] = 0.f;
}

// in-degree over targets (col)
__global__ void k_deg(const int* __restrict__ col, int e_cnt) {
    int e = blockIdx.x * blockDim.x + threadIdx.x;
    if (e < e_cnt) atomicAdd(&d_degi[col[e]], 1);
}

// ---------------------------------------------------------------- scan (exclusive)
__global__ void k_scan1(int n) {
    __shared__ int s[SCAN_BS];
    int t = threadIdx.x, i = blockIdx.x * SCAN_BS + t;
    int v = (i < n) ? d_degi[i] : 0;
    s[t] = v;
    __syncthreads();
#pragma unroll
    for (int o = 1; o < SCAN_BS; o <<= 1) {
        int x = (t >= o) ? s[t - o] : 0;
        __syncthreads();
        s[t] += x;
        __syncthreads();
    }
    if (i < n) d_off[i] = s[t] - v;               // exclusive within block
    if (t == SCAN_BS - 1) d_bsum[blockIdx.x] = s[t];
}

__global__ void k_scan2(int nb) {
    __shared__ int s[1024];
    int t = threadIdx.x;
    int v = (t < nb) ? d_bsum[t] : 0;
    s[t] = v;
    __syncthreads();
#pragma unroll
    for (int o = 1; o < 1024; o <<= 1) {
        int x = (t >= o) ? s[t - o] : 0;
        __syncthreads();
        s[t] += x;
        __syncthreads();
    }
    if (t < nb) d_bsum[t] = s[t] - v;             // exclusive block offsets
}

__global__ void k_scan3(int n) {
    int i = blockIdx.x * blockDim.x + threadIdx.x;
    if (i >= n) return;
    int off = d_off[i] + d_bsum[i / SCAN_BS];
    d_off[i] = off;
    d_cursor[i] = off;
    d_dinv[i] = rsqrtf((float)d_degi[i] + 1.0f);  // +1 self-loop
}

// CSR fill: group source indices by target
__global__ void k_fill(const int* __restrict__ rowi, const int* __restrict__ coli, int e_cnt) {
    int e = blockIdx.x * blockDim.x + threadIdx.x;
    if (e >= e_cnt) return;
    int c = coli[e];
    int pos = atomicAdd(&d_cursor[c], 1);
    d_csr[pos] = rowi[e];
}

// ---------------------------------------------------------------- embed
__global__ void k_embed(const int* __restrict__ x, const float* __restrict__ emb, int n) {
    int i = blockIdx.x * blockDim.x + threadIdx.x;
    if (i >= n * 16) return;
    int nd = i >> 4, j = i & 15;
    int v = __ldg(&x[nd]);
    ((float4*)d_h)[i] = __ldg(&((const float4*)emb)[v * 16 + j]);
}

// ---------------------------------------------------------------- GEMM: u = (h @ W) * dinv
__global__ void __launch_bounds__(256) k_gemm(const float* __restrict__ W, int n) {
    __shared__ float4 sW[64 * 16];
    __shared__ float sh[64 * 68];

    int tid = threadIdx.x;
    int row0 = blockIdx.x * 64;

    const float4* W4 = (const float4*)W;
#pragma unroll
    for (int i = 0; i < 4; i++) sW[tid + 256 * i] = W4[tid + 256 * i];

    const float4* h4 = (const float4*)d_h;
#pragma unroll
    for (int i = 0; i < 4; i++) {
        int l = tid + 256 * i;
        int r = l >> 4, c4 = l & 15;
        float4 v = make_float4(0.f, 0.f, 0.f, 0.f);
        if (row0 + r < n) v = h4[(row0 + r) * 16 + c4];
        ((float4*)sh)[r * 17 + c4] = v;
    }
    __syncthreads();

    int r = tid >> 2, q = tid & 3;
    float4 a0 = make_float4(0.f, 0.f, 0.f, 0.f), a1 = a0, a2 = a0, a3 = a0;

#pragma unroll 16
    for (int k = 0; k < 64; k++) {
        float hv = sh[r * 68 + k];
        float4 w0 = sW[k * 16 + q * 4 + 0];
        float4 w1 = sW[k * 16 + q * 4 + 1];
        float4 w2 = sW[k * 16 + q * 4 + 2];
        float4 w3 = sW[k * 16 + q * 4 + 3];
        a0.x = fmaf(hv, w0.x, a0.x); a0.y = fmaf(hv, w0.y, a0.y);
        a0.z = fmaf(hv, w0.z, a0.z); a0.w = fmaf(hv, w0.w, a0.w);
        a1.x = fmaf(hv, w1.x, a1.x); a1.y = fmaf(hv, w1.y, a1.y);
        a1.z = fmaf(hv, w1.z, a1.z); a1.w = fmaf(hv, w1.w, a1.w);
        a2.x = fmaf(hv, w2.x, a2.x); a2.y = fmaf(hv, w2.y, a2.y);
        a2.z = fmaf(hv, w2.z, a2.z); a2.w = fmaf(hv, w2.w, a2.w);
        a3.x = fmaf(hv, w3.x, a3.x); a3.y = fmaf(hv, w3.y, a3.y);
        a3.z = fmaf(hv, w3.z, a3.z); a3.w = fmaf(hv, w3.w, a3.w);
    }

    int row = row0 + r;
    if (row < n) {
        float dv = __ldg(&d_dinv[row]);
        float4* u4 = (float4*)d_u;
        a0.x *= dv; a0.y *= dv; a0.z *= dv; a0.w *= dv;
        a1.x *= dv; a1.y *= dv; a1.z *= dv; a1.w *= dv;
        a2.x *= dv; a2.y *= dv; a2.z *= dv; a2.w *= dv;
        a3.x *= dv; a3.y *= dv; a3.z *= dv; a3.w *= dv;
        u4[row * 16 + q * 4 + 0] = a0;
        u4[row * 16 + q * 4 + 1] = a1;
        u4[row * 16 + q * 4 + 2] = a2;
        u4[row * 16 + q * 4 + 3] = a3;
    }
}

// ---------------------------------------------------------------- gather + epilogue
// 16 threads/node. acc = u[self] + sum_{src in CSR(node)} u[src]
// h_new = relu(dinv*acc + b);  h = layer ? h + h_new : h_new
__global__ void __launch_bounds__(256) k_gather(const float* __restrict__ b, int layer, int n) {
    int idx = blockIdx.x * blockDim.x + threadIdx.x;
    int nd = idx >> 4;
    if (nd >= n) return;
    int p = idx & 15;

    int beg = __ldg(&d_off[nd]);
    int deg = __ldg(&d_degi[nd]);
    const float4* u4 = (const float4*)d_u;

    float4 acc = u4[nd * 16 + p];  // self-loop term

    int k = 0;
    for (; k + 4 <= deg; k += 4) {
        int s0 = __ldg(&d_csr[beg + k + 0]);
        int s1 = __ldg(&d_csr[beg + k + 1]);
        int s2 = __ldg(&d_csr[beg + k + 2]);
        int s3 = __ldg(&d_csr[beg + k + 3]);
        float4 v0 = __ldg(&u4[s0 * 16 + p]);
        float4 v1 = __ldg(&u4[s1 * 16 + p]);
        float4 v2 = __ldg(&u4[s2 * 16 + p]);
        float4 v3 = __ldg(&u4[s3 * 16 + p]);
        acc.x += v0.x + v1.x + v2.x + v3.x;
        acc.y += v0.y + v1.y + v2.y + v3.y;
        acc.z += v0.z + v1.z + v2.z + v3.z;
        acc.w += v0.w + v1.w + v2.w + v3.w;
    }
    for (; k < deg; k++) {
        int s0 = __ldg(&d_csr[beg + k]);
        float4 v0 = __ldg(&u4[s0 * 16 + p]);
        acc.x += v0.x; acc.y += v0.y; acc.z += v0.z; acc.w += v0.w;
    }

    float dv = __ldg(&d_dinv[nd]);
    float4 bb = __ldg(&((const float4*)b)[p]);

    float4 v;
    v.x = fmaxf(fmaf(dv, acc.x, bb.x), 0.f);
    v.y = fmaxf(fmaf(dv, acc.y, bb.y), 0.f);
    v.z = fmaxf(fmaf(dv, acc.z, bb.z), 0.f);
    v.w = fmaxf(fmaf(dv, acc.w, bb.w), 0.f);

    float4* h4 = (float4*)d_h;
    if (layer != 0) {
        float4 hh = h4[nd * 16 + p];
        v.x += hh.x; v.y += hh.y; v.z += hh.z; v.w += hh.w;
    }
    h4[nd * 16 + p] = v;
}

// ---------------------------------------------------------------- pool
__global__ void k_pool(const int* __restrict__ batch, int n) {
    int i = blockIdx.x * blockDim.x + threadIdx.x;
    if (i >= n * 16) return;
    int nd = i >> 4, p = i & 15;
    int g = __ldg(&batch[nd]);
    float4 v = ((const float4*)d_h)[i];
    red4(&d_sums[g * 64 + p * 4], v);
    if (p == 0) atomicAdd(&d_cnt[g], 1.0f);
}

// ---------------------------------------------------------------- MLP head
__global__ void k_mlp(const float* __restrict__ w1, const float* __restrict__ b1,
                      const float* __restrict__ w2, const float* __restrict__ b2,
                      const float* __restrict__ w3, const float* __restrict__ b3,
                      float* __restrict__ out) {
    int g = blockIdx.x * blockDim.x + threadIdx.x;
    if (g >= GG) return;

    float inv = 1.0f / fmaxf(d_cnt[g], 1.0f);
    float gin[64];
#pragma unroll
    for (int k = 0; k < 64; k++) gin[k] = d_sums[g * 64 + k] * inv;

    float a1[32];
#pragma unroll
    for (int j = 0; j < 32; j++) {
        float s = __ldg(&b1[j]);
#pragma unroll
        for (int k = 0; k < 64; k++) s = fmaf(gin[k], __ldg(&w1[k * 32 + j]), s);
        a1[j] = fmaxf(s, 0.f);
    }
    float a2[16];
#pragma unroll
    for (int j = 0; j < 16; j++) {
        float s = __ldg(&b2[j]);
#pragma unroll
        for (int k = 0; k < 32; k++) s = fmaf(a1[k], __ldg(&w2[k * 16 + j]), s);
        a2[j] = fmaxf(s, 0.f);
    }
    float s = __ldg(&b3[0]);
#pragma unroll
    for (int k = 0; k < 16; k++) s = fmaf(a2[k], __ldg(&w3[k]), s);
    out[g] = s;
}

// ---------------------------------------------------------------- launch
extern "C" void kernel_launch(void* const* d_in, const int* in_sizes, int n_in,
                              void* d_out, int out_size) {
    const int*   x      = (const int*)d_in[0];
    const int*   ei     = (const int*)d_in[1];
    const int*   batch  = (const int*)d_in[2];
    const float* emb    = (const float*)d_in[3];
    const float* conv_w = (const float*)d_in[4];
    const float* conv_b = (const float*)d_in[5];
    const float* w1     = (const float*)d_in[6];
    const float* b1     = (const float*)d_in[7];
    const float* w2     = (const float*)d_in[8];
    const float* b2     = (const float*)d_in[9];
    const float* w3     = (const float*)d_in[10];
    const float* b3     = (const float*)d_in[11];
    float* out = (float*)d_out;

    int n = in_sizes[0];       // 100000
    int e = in_sizes[1] / 2;   // 3200000
    const int* row = ei;       // source
    const int* col = ei + e;   // target

    int tb = 256;
    int g_nh = (n * 16 + tb - 1) / tb;
    int g_e  = (e + tb - 1) / tb;
    int g_n  = (n + tb - 1) / tb;
    int g_rows = (n + 63) / 64;
    int nb_scan = (n + SCAN_BS - 1) / SCAN_BS;

    k_init<<<g_nh, tb>>>(n);
    k_deg<<<g_e, tb>>>(col, e);
    k_scan1<<<nb_scan, SCAN_BS>>>(n);
    k_scan2<<<1, 1024>>>(nb_scan);
    k_scan3<<<g_n, tb>>>(n);
    k_fill<<<g_e, tb>>>(row, col, e);
    k_embed<<<g_nh, tb>>>(x, emb, n);

    for (int l = 0; l < 3; l++) {
        k_gemm<<<g_rows, tb>>>(conv_w + l * HH * HH, n);
        k_gather<<<g_nh, tb>>>(conv_b + l * HH, l, n);
    }

    k_pool<<<g_nh, tb>>>(batch, n);
    k_mlp<<<(GG + tb - 1) / tb, tb>>>(w1, b1, w2, b2, w3, b3, out);
}

// round 3
// speedup vs baseline: 1.8079x; 1.1529x over previous
#include <cuda_runtime.h>
#include <cuda_fp16.h>

#define NN 100000
#define EE 3200000
#define GG 2048
#define HH 64
#define SCAN_BS 512

// Scratch (device globals — no allocation allowed)
__device__ float   d_h[NN * HH];      // node features (fp32)
__device__ __half  d_uh[NN * HH];     // (h @ W) * dinv, fp16 (128B/row)
__device__ float   d_dinv[NN];        // rsqrt(deg+1)
__device__ int     d_degi[NN];        // in-degree (targets)
__device__ int     d_off[NN];         // CSR offsets
__device__ int     d_epos[EE];        // per-edge rank within its target
__device__ int     d_csr[EE];         // source node per incoming edge, grouped by target
__device__ int     d_bsum[1024];      // scan block sums
__device__ float   d_sums[GG * HH];   // pooled sums
__device__ float   d_cnt[GG];         // pooled counts

__device__ __forceinline__ void red4(float* addr, float4 v) {
    asm volatile("red.global.add.v4.f32 [%0], {%1,%2,%3,%4};"
                 :: "l"(addr), "f"(v.x), "f"(v.y), "f"(v.z), "f"(v.w)
                 : "memory");
}

// ---------------------------------------------------------------- init
__global__ void k_init(int n) {
    int i = blockIdx.x * blockDim.x + threadIdx.x;
    if (i < n) d_degi[i] = 0;
    if (i < GG * (HH / 4)) ((float4*)d_sums)[i] = make_float4(0.f, 0.f, 0.f, 0.f);
    if (i < GG) d_cnt[i] = 0.f;
}

// in-degree over targets + per-edge rank
__global__ void k_deg(const int* __restrict__ col, int e_cnt) {
    int e = blockIdx.x * blockDim.x + threadIdx.x;
    if (e >= e_cnt) return;
    d_epos[e] = atomicAdd(&d_degi[col[e]], 1);
}

// ---------------------------------------------------------------- scan (exclusive)
__global__ void k_scan1(int n) {
    __shared__ int s[SCAN_BS];
    int t = threadIdx.x, i = blockIdx.x * SCAN_BS + t;
    int v = (i < n) ? d_degi[i] : 0;
    s[t] = v;
    __syncthreads();
#pragma unroll
    for (int o = 1; o < SCAN_BS; o <<= 1) {
        int x = (t >= o) ? s[t - o] : 0;
        __syncthreads();
        s[t] += x;
        __syncthreads();
    }
    if (i < n) d_off[i] = s[t] - v;
    if (t == SCAN_BS - 1) d_bsum[blockIdx.x] = s[t];
}

__global__ void k_scan2(int nb) {
    __shared__ int s[1024];
    int t = threadIdx.x;
    int v = (t < nb) ? d_bsum[t] : 0;
    s[t] = v;
    __syncthreads();
#pragma unroll
    for (int o = 1; o < 1024; o <<= 1) {
        int x = (t >= o) ? s[t - o] : 0;
        __syncthreads();
        s[t] += x;
        __syncthreads();
    }
    if (t < nb) d_bsum[t] = s[t] - v;
}

__global__ void k_scan3(int n) {
    int i = blockIdx.x * blockDim.x + threadIdx.x;
    if (i >= n) return;
    int off = d_off[i] + d_bsum[i / SCAN_BS];
    d_off[i] = off;
    d_dinv[i] = rsqrtf((float)d_degi[i] + 1.0f);  // +1 self-loop
}

// CSR fill: plain store via precomputed rank (no atomics)
__global__ void k_fill(const int* __restrict__ rowi, const int* __restrict__ coli, int e_cnt) {
    int e = blockIdx.x * blockDim.x + threadIdx.x;
    if (e >= e_cnt) return;
    d_csr[__ldg(&d_off[coli[e]]) + d_epos[e]] = rowi[e];
}

// ---------------------------------------------------------------- GEMM: u = (h @ W) * dinv  -> fp16
// layer 0 reads h rows from emb[x[row]] (fused embedding)
__global__ void __launch_bounds__(256) k_gemm(const float* __restrict__ W,
                                              const int* __restrict__ x,
                                              const float* __restrict__ emb,
                                              int layer, int n) {
    __shared__ float4 sW[64 * 16];
    __shared__ float sh[64 * 68];

    int tid = threadIdx.x;
    int row0 = blockIdx.x * 64;

    const float4* W4 = (const float4*)W;
#pragma unroll
    for (int i = 0; i < 4; i++) sW[tid + 256 * i] = W4[tid + 256 * i];

    const float4* h4 = (const float4*)d_h;
    const float4* emb4 = (const float4*)emb;
#pragma unroll
    for (int i = 0; i < 4; i++) {
        int l = tid + 256 * i;
        int r = l >> 4, c4 = l & 15;
        int grow = row0 + r;
        float4 v = make_float4(0.f, 0.f, 0.f, 0.f);
        if (grow < n) {
            if (layer == 0) {
                int vx = __ldg(&x[grow]);
                v = __ldg(&emb4[vx * 16 + c4]);
            } else {
                v = h4[grow * 16 + c4];
            }
        }
        ((float4*)sh)[r * 17 + c4] = v;
    }
    __syncthreads();

    int r = tid >> 2, q = tid & 3;
    float4 a0 = make_float4(0.f, 0.f, 0.f, 0.f), a1 = a0, a2 = a0, a3 = a0;

#pragma unroll 16
    for (int k = 0; k < 64; k++) {
        float hv = sh[r * 68 + k];
        float4 w0 = sW[k * 16 + q * 4 + 0];
        float4 w1 = sW[k * 16 + q * 4 + 1];
        float4 w2 = sW[k * 16 + q * 4 + 2];
        float4 w3 = sW[k * 16 + q * 4 + 3];
        a0.x = fmaf(hv, w0.x, a0.x); a0.y = fmaf(hv, w0.y, a0.y);
        a0.z = fmaf(hv, w0.z, a0.z); a0.w = fmaf(hv, w0.w, a0.w);
        a1.x = fmaf(hv, w1.x, a1.x); a1.y = fmaf(hv, w1.y, a1.y);
        a1.z = fmaf(hv, w1.z, a1.z); a1.w = fmaf(hv, w1.w, a1.w);
        a2.x = fmaf(hv, w2.x, a2.x); a2.y = fmaf(hv, w2.y, a2.y);
        a2.z = fmaf(hv, w2.z, a2.z); a2.w = fmaf(hv, w2.w, a2.w);
        a3.x = fmaf(hv, w3.x, a3.x); a3.y = fmaf(hv, w3.y, a3.y);
        a3.z = fmaf(hv, w3.z, a3.z); a3.w = fmaf(hv, w3.w, a3.w);
    }

    int row = row0 + r;
    if (row < n) {
        float dv = __ldg(&d_dinv[row]);
        uint4 o0, o1;
        __half2 t0, t1;
        t0 = __float22half2_rn(make_float2(a0.x * dv, a0.y * dv));
        t1 = __float22half2_rn(make_float2(a0.z * dv, a0.w * dv));
        o0.x = *(unsigned*)&t0; o0.y = *(unsigned*)&t1;
        t0 = __float22half2_rn(make_float2(a1.x * dv, a1.y * dv));
        t1 = __float22half2_rn(make_float2(a1.z * dv, a1.w * dv));
        o0.z = *(unsigned*)&t0; o0.w = *(unsigned*)&t1;
        t0 = __float22half2_rn(make_float2(a2.x * dv, a2.y * dv));
        t1 = __float22half2_rn(make_float2(a2.z * dv, a2.w * dv));
        o1.x = *(unsigned*)&t0; o1.y = *(unsigned*)&t1;
        t0 = __float22half2_rn(make_float2(a3.x * dv, a3.y * dv));
        t1 = __float22half2_rn(make_float2(a3.z * dv, a3.w * dv));
        o1.z = *(unsigned*)&t0; o1.w = *(unsigned*)&t1;
        uint4* U = (uint4*)d_uh;           // 8 uint4 per row
        U[row * 8 + q * 2 + 0] = o0;
        U[row * 8 + q * 2 + 1] = o1;
    }
}

// ---------------------------------------------------------------- gather + epilogue
// 8 threads/node, each owns 8 channels (one uint4 = 8 halves). fp32 accumulate.
__global__ void __launch_bounds__(256) k_gather(const float* __restrict__ b, int layer, int n) {
    int idx = blockIdx.x * blockDim.x + threadIdx.x;
    int nd = idx >> 3;
    if (nd >= n) return;
    int p = idx & 7;

    int beg = __ldg(&d_off[nd]);
    int deg = __ldg(&d_degi[nd]);
    const uint4* U = (const uint4*)d_uh;

    float a0 = 0.f, a1 = 0.f, a2 = 0.f, a3 = 0.f,
          a4 = 0.f, a5 = 0.f, a6 = 0.f, a7 = 0.f;

#define ACC8(v) do {                                              \
        float2 f;                                                 \
        f = __half22float2(*(__half2*)&(v).x); a0 += f.x; a1 += f.y; \
        f = __half22float2(*(__half2*)&(v).y); a2 += f.x; a3 += f.y; \
        f = __half22float2(*(__half2*)&(v).z); a4 += f.x; a5 += f.y; \
        f = __half22float2(*(__half2*)&(v).w); a6 += f.x; a7 += f.y; \
    } while (0)

    uint4 vs = U[nd * 8 + p];  // self-loop term
    ACC8(vs);

    int k = 0;
    for (; k + 4 <= deg; k += 4) {
        int s0 = __ldg(&d_csr[beg + k + 0]);
        int s1 = __ldg(&d_csr[beg + k + 1]);
        int s2 = __ldg(&d_csr[beg + k + 2]);
        int s3 = __ldg(&d_csr[beg + k + 3]);
        uint4 v0 = __ldg(&U[s0 * 8 + p]);
        uint4 v1 = __ldg(&U[s1 * 8 + p]);
        uint4 v2 = __ldg(&U[s2 * 8 + p]);
        uint4 v3 = __ldg(&U[s3 * 8 + p]);
        ACC8(v0); ACC8(v1); ACC8(v2); ACC8(v3);
    }
    for (; k < deg; k++) {
        int s0 = __ldg(&d_csr[beg + k]);
        uint4 v0 = __ldg(&U[s0 * 8 + p]);
        ACC8(v0);
    }
#undef ACC8

    float dv = __ldg(&d_dinv[nd]);
    const float4* b4 = (const float4*)b;
    float4 bb0 = __ldg(&b4[p * 2 + 0]);
    float4 bb1 = __ldg(&b4[p * 2 + 1]);

    float4 v0, v1;
    v0.x = fmaxf(fmaf(dv, a0, bb0.x), 0.f);
    v0.y = fmaxf(fmaf(dv, a1, bb0.y), 0.f);
    v0.z = fmaxf(fmaf(dv, a2, bb0.z), 0.f);
    v0.w = fmaxf(fmaf(dv, a3, bb0.w), 0.f);
    v1.x = fmaxf(fmaf(dv, a4, bb1.x), 0.f);
    v1.y = fmaxf(fmaf(dv, a5, bb1.y), 0.f);
    v1.z = fmaxf(fmaf(dv, a6, bb1.z), 0.f);
    v1.w = fmaxf(fmaf(dv, a7, bb1.w), 0.f);

    float4* h4 = (float4*)d_h;
    if (layer != 0) {
        float4 h0 = h4[nd * 16 + p * 2 + 0];
        float4 h1 = h4[nd * 16 + p * 2 + 1];
        v0.x += h0.x; v0.y += h0.y; v0.z += h0.z; v0.w += h0.w;
        v1.x += h1.x; v1.y += h1.y; v1.z += h1.z; v1.w += h1.w;
    }
    h4[nd * 16 + p * 2 + 0] = v0;
    h4[nd * 16 + p * 2 + 1] = v1;
}

// ---------------------------------------------------------------- pool
__global__ void k_pool(const int* __restrict__ batch, int n) {
    int i = blockIdx.x * blockDim.x + threadIdx.x;
    if (i >= n * 16) return;
    int nd = i >> 4, p = i & 15;
    int g = __ldg(&batch[nd]);
    float4 v = ((const float4*)d_h)[i];
    red4(&d_sums[g * 64 + p * 4], v);
    if (p == 0) atomicAdd(&d_cnt[g], 1.0f);
}

// ---------------------------------------------------------------- MLP head
__global__ void k_mlp(const float* __restrict__ w1, const float* __restrict__ b1,
                      const float* __restrict__ w2, const float* __restrict__ b2,
                      const float* __restrict__ w3, const float* __restrict__ b3,
                      float* __restrict__ out) {
    int g = blockIdx.x * blockDim.x + threadIdx.x;
    if (g >= GG) return;

    float inv = 1.0f / fmaxf(d_cnt[g], 1.0f);
    float gin[64];
#pragma unroll
    for (int k = 0; k < 64; k++) gin[k] = d_sums[g * 64 + k] * inv;

    float a1[32];
#pragma unroll
    for (int j = 0; j < 32; j++) {
        float s = __ldg(&b1[j]);
#pragma unroll
        for (int k = 0; k < 64; k++) s = fmaf(gin[k], __ldg(&w1[k * 32 + j]), s);
        a1[j] = fmaxf(s, 0.f);
    }
    float a2[16];
#pragma unroll
    for (int j = 0; j < 16; j++) {
        float s = __ldg(&b2[j]);
#pragma unroll
        for (int k = 0; k < 32; k++) s = fmaf(a1[k], __ldg(&w2[k * 16 + j]), s);
        a2[j] = fmaxf(s, 0.f);
    }
    float s = __ldg(&b3[0]);
#pragma unroll
    for (int k = 0; k < 16; k++) s = fmaf(a2[k], __ldg(&w3[k]), s);
    out[g] = s;
}

// ---------------------------------------------------------------- launch
extern "C" void kernel_launch(void* const* d_in, const int* in_sizes, int n_in,
                              void* d_out, int out_size) {
    const int*   x      = (const int*)d_in[0];
    const int*   ei     = (const int*)d_in[1];
    const int*   batch  = (const int*)d_in[2];
    const float* emb    = (const float*)d_in[3];
    const float* conv_w = (const float*)d_in[4];
    const float* conv_b = (const float*)d_in[5];
    const float* w1     = (const float*)d_in[6];
    const float* b1     = (const float*)d_in[7];
    const float* w2     = (const float*)d_in[8];
    const float* b2     = (const float*)d_in[9];
    const float* w3     = (const float*)d_in[10];
    const float* b3     = (const float*)d_in[11];
    float* out = (float*)d_out;

    int n = in_sizes[0];       // 100000
    int e = in_sizes[1] / 2;   // 3200000
    const int* row = ei;       // source
    const int* col = ei + e;   // target

    int tb = 256;
    int g_nh = (n * 16 + tb - 1) / tb;
    int g_n8 = (n * 8 + tb - 1) / tb;
    int g_e  = (e + tb - 1) / tb;
    int g_n  = (n + tb - 1) / tb;
    int g_rows = (n + 63) / 64;
    int nb_scan = (n + SCAN_BS - 1) / SCAN_BS;

    k_init<<<g_nh, tb>>>(n);
    k_deg<<<g_e, tb>>>(col, e);
    k_scan1<<<nb_scan, SCAN_BS>>>(n);
    k_scan2<<<1, 1024>>>(nb_scan);
    k_scan3<<<g_n, tb>>>(n);
    k_fill<<<g_e, tb>>>(row, col, e);

    for (int l = 0; l < 3; l++) {
        k_gemm<<<g_rows, tb>>>(conv_w + l * HH * HH, x, emb, l, n);
        k_gather<<<g_n8, tb>>>(conv_b + l * HH, l, n);
    }

    k_pool<<<g_nh, tb>>>(batch, n);
    k_mlp<<<(GG + tb - 1) / tb, tb>>>(w1, b1, w2, b2, w3, b3, out);
}